// round 13
// baseline (speedup 1.0000x reference)
#include <cuda_runtime.h>
#include <cuda_bf16.h>
#include <cstdint>
#include <math.h>

// Problem constants
#define BB 2
#define LL 2048
#define DD 768
#define HH 12
#define HD 64
#define ND3 2304   // 3*D
#define KDIM 768

typedef unsigned long long u64;
typedef unsigned int u32;

// Scratch (device globals: allocation-free rule)
__device__ float g_Q[BB * HH * LL * HD];
__device__ float g_K[BB * HH * LL * HD];
__device__ float g_V[BB * HH * LL * HD];

// bf16 hi/lo split operands
__device__ __nv_bfloat16 gXhi[BB * LL * DD], gXlo[BB * LL * DD];
__device__ __nv_bfloat16 gWqkv_hi[ND3 * KDIM], gWqkv_lo[ND3 * KDIM];   // [N][K]
__device__ __nv_bfloat16 gWout_hi[DD * KDIM],  gWout_lo[DD * KDIM];    // [N][K]
__device__ __nv_bfloat16 gAhi[BB * LL * DD],   gAlo[BB * LL * DD];
// RoPE'd Q/K, [b][h][l][d] — single bf16 (S-path error budget)
__device__ __nv_bfloat16 gQhi[BB * HH * LL * HD];
__device__ __nv_bfloat16 gKhi[BB * HH * LL * HD];
// V transposed, [b][h][d][l] — hi/lo (PV feeds output directly; keep split)
__device__ __nv_bfloat16 gVthi[BB * HH * HD * LL], gVtlo[BB * HH * HD * LL];

// ---------------------------------------------------------------------------
// PTX helpers
// ---------------------------------------------------------------------------
__device__ __forceinline__ u32 smem_u32(const void* p) {
    u32 a;
    asm("{ .reg .u64 t; cvta.to.shared.u64 t, %1; cvt.u32.u64 %0, t; }"
        : "=r"(a) : "l"(p));
    return a;
}
__device__ __forceinline__ void ldsm4(u32* r, u32 addr) {
    asm volatile("ldmatrix.sync.aligned.m8n8.x4.shared.b16 {%0,%1,%2,%3}, [%4];"
                 : "=r"(r[0]), "=r"(r[1]), "=r"(r[2]), "=r"(r[3]) : "r"(addr));
}
__device__ __forceinline__ void mma16816(float* c, const u32* a, const u32* b) {
    asm volatile(
        "mma.sync.aligned.m16n8k16.row.col.f32.bf16.bf16.f32 "
        "{%0,%1,%2,%3}, {%4,%5,%6,%7}, {%8,%9}, {%0,%1,%2,%3};"
        : "+f"(c[0]), "+f"(c[1]), "+f"(c[2]), "+f"(c[3])
        : "r"(a[0]), "r"(a[1]), "r"(a[2]), "r"(a[3]), "r"(b[0]), "r"(b[1]));
}

__device__ __forceinline__ void split_bf16(float x, __nv_bfloat16& h, __nv_bfloat16& l) {
    h = __float2bfloat16(x);
    l = __float2bfloat16(x - __bfloat162float(h));
}

// ---------------------------------------------------------------------------
// Conversion kernels
// ---------------------------------------------------------------------------
__global__ __launch_bounds__(256) void xconv_kernel(
    const float* __restrict__ src, __nv_bfloat16* __restrict__ hi,
    __nv_bfloat16* __restrict__ lo)
{
    const int i = blockIdx.x * 256 + threadIdx.x;
    __nv_bfloat16 h, l;
    split_bf16(src[i], h, l);
    hi[i] = h; lo[i] = l;
}

// W[K][N] row-major -> hi/lo[N][K] (transposed, bf16 split)
__global__ __launch_bounds__(256) void wconv_kernel(
    const float* __restrict__ W, __nv_bfloat16* __restrict__ hi,
    __nv_bfloat16* __restrict__ lo, int K, int N)
{
    __shared__ float t[32][33];
    const int n0 = blockIdx.x * 32, k0 = blockIdx.y * 32;
    const int tx = threadIdx.x, ty = threadIdx.y;   // 32 x 8
    #pragma unroll
    for (int i = 0; i < 4; i++)
        t[ty + 8 * i][tx] = W[(size_t)(k0 + ty + 8 * i) * N + n0 + tx];
    __syncthreads();
    #pragma unroll
    for (int i = 0; i < 4; i++) {
        const int n = n0 + ty + 8 * i, k = k0 + tx;
        float x = t[tx][ty + 8 * i];
        __nv_bfloat16 h, l;
        split_bf16(x, h, l);
        hi[(size_t)n * K + k] = h;
        lo[(size_t)n * K + k] = l;
    }
}

// g_V [bh][l][64] fp32 -> gVt hi/lo [bh][64][LL] bf16 (transpose + split)
__global__ void vconv_kernel()   // grid (LL/32, HD/32, BH), block (32,8)
{
    __shared__ float t[32][33];
    const int l0 = blockIdx.x * 32, d0 = blockIdx.y * 32;
    const int bh = blockIdx.z;
    const int tx = threadIdx.x, ty = threadIdx.y;
    const float* V = g_V + (size_t)bh * LL * HD;
    #pragma unroll
    for (int i = 0; i < 4; i++)
        t[ty + 8 * i][tx] = V[(size_t)(l0 + ty + 8 * i) * HD + d0 + tx];
    __syncthreads();
    #pragma unroll
    for (int i = 0; i < 4; i++) {
        const int d = d0 + ty + 8 * i, l = l0 + tx;
        float x = t[tx][ty + 8 * i];
        __nv_bfloat16 h, lo_;
        split_bf16(x, h, lo_);
        const size_t o = (size_t)bh * HD * LL + (size_t)d * LL + l;
        gVthi[o] = h;
        gVtlo[o] = lo_;
    }
}

// ---------------------------------------------------------------------------
// HMMA GEMM mainloop. TERMS=3: full hi/lo 3-term split. TERMS=1: hi*hi only
// (Q/K columns — error reaches output only via exp(s/45), 45x attenuated).
// ---------------------------------------------------------------------------
struct GemmSmem {
    __nv_bfloat16 A[2][128][40];
    __nv_bfloat16 B[2][128][40];
};

template<int TERMS>
__device__ __forceinline__ void hmma_mainloop(
    const __nv_bfloat16* __restrict__ Ahi, const __nv_bfloat16* __restrict__ Alo,
    const __nv_bfloat16* __restrict__ Bhi, const __nv_bfloat16* __restrict__ Blo,
    GemmSmem& sm, int row0, int col0, float acc[4][4][4])
{
    const int tid = threadIdx.x;
    const int lane = tid & 31, wid = tid >> 5;
    const int warp_m = wid & 1, warp_n = wid >> 1;

    for (int kt = 0; kt < KDIM / 32; kt++) {
        #pragma unroll
        for (int t = 0; t < 2; t++) {
            const int idx = tid + t * 256;
            const int r = idx >> 2, c4 = idx & 3;
            const size_t ga = (size_t)(row0 + r) * KDIM + kt * 32 + c4 * 8;
            const size_t gb = (size_t)(col0 + r) * KDIM + kt * 32 + c4 * 8;
            *(uint4*)&sm.A[0][r][c4 * 8] = *(const uint4*)(Ahi + ga);
            *(uint4*)&sm.B[0][r][c4 * 8] = *(const uint4*)(Bhi + gb);
            if (TERMS == 3) {
                *(uint4*)&sm.A[1][r][c4 * 8] = *(const uint4*)(Alo + ga);
                *(uint4*)&sm.B[1][r][c4 * 8] = *(const uint4*)(Blo + gb);
            }
        }
        __syncthreads();

        #pragma unroll
        for (int ks = 0; ks < 2; ks++) {
            u32 afh[4][4], afl[4][4];
            #pragma unroll
            for (int mt = 0; mt < 4; mt++) {
                const int mr = warp_m * 64 + mt * 16 + (lane & 15);
                const int kc = ks * 16 + (lane >> 4) * 8;
                ldsm4(afh[mt], smem_u32(&sm.A[0][mr][kc]));
                if (TERMS == 3) ldsm4(afl[mt], smem_u32(&sm.A[1][mr][kc]));
            }
            u32 bfh[2][4], bfl[2][4];
            #pragma unroll
            for (int np = 0; np < 2; np++) {
                const int nr = warp_n * 32 + np * 16 + ((lane >> 4) << 3) + (lane & 7);
                const int kc = ks * 16 + ((lane >> 3) & 1) * 8;
                ldsm4(bfh[np], smem_u32(&sm.B[0][nr][kc]));
                if (TERMS == 3) ldsm4(bfl[np], smem_u32(&sm.B[1][nr][kc]));
            }
            #pragma unroll
            for (int mt = 0; mt < 4; mt++) {
                #pragma unroll
                for (int nt = 0; nt < 4; nt++) {
                    const u32* bh = &bfh[nt >> 1][(nt & 1) * 2];
                    mma16816(acc[mt][nt], afh[mt], bh);
                    if (TERMS == 3) {
                        const u32* bl = &bfl[nt >> 1][(nt & 1) * 2];
                        mma16816(acc[mt][nt], afh[mt], bl);
                        mma16816(acc[mt][nt], afl[mt], bh);
                    }
                }
            }
        }
        __syncthreads();
    }
}

// ---------------------------------------------------------------------------
// Kernel: QKV projection via HMMA. Q/K columns (bx<12): 1-term; V: 3-term.
// ---------------------------------------------------------------------------
__global__ __launch_bounds__(256) void qkv_mma_kernel(const float* __restrict__ bias)
{
    __shared__ GemmSmem sm;
    const int tid = threadIdx.x;
    const int lane = tid & 31, wid = tid >> 5;
    const int warp_m = wid & 1, warp_n = wid >> 1;
    const int row0 = blockIdx.y * 128, col0 = blockIdx.x * 128;

    float acc[4][4][4];
    #pragma unroll
    for (int i = 0; i < 4; i++)
        #pragma unroll
        for (int j = 0; j < 4; j++)
            #pragma unroll
            for (int k = 0; k < 4; k++) acc[i][j][k] = 0.f;

    if (blockIdx.x < 12)
        hmma_mainloop<1>(gXhi, gXlo, gWqkv_hi, gWqkv_lo, sm, row0, col0, acc);
    else
        hmma_mainloop<3>(gXhi, gXlo, gWqkv_hi, gWqkv_lo, sm, row0, col0, acc);

    #pragma unroll
    for (int mt = 0; mt < 4; mt++) {
        #pragma unroll
        for (int nt = 0; nt < 4; nt++) {
            const int c = col0 + warp_n * 32 + nt * 8 + (lane & 3) * 2;
            const int which = c / DD;
            const int rem = c - which * DD;
            const int h = rem >> 6, d = rem & 63;
            float* dst = (which == 0) ? g_Q : (which == 1) ? g_K : g_V;
            const float b0 = bias[c], b1 = bias[c + 1];
            #pragma unroll
            for (int half = 0; half < 2; half++) {
                const int r = row0 + warp_m * 64 + mt * 16 + (lane >> 2) + half * 8;
                const int bb = r >> 11, l = r & 2047;
                float2 v = make_float2(acc[mt][nt][half * 2] + b0,
                                       acc[mt][nt][half * 2 + 1] + b1);
                *(float2*)(dst + (((size_t)(bb * HH + h)) * LL + l) * HD + d) = v;
            }
        }
    }
}

// ---------------------------------------------------------------------------
// Kernel: output projection via HMMA (3-term; feeds output directly).
// ---------------------------------------------------------------------------
__global__ __launch_bounds__(256) void out_mma_kernel(
    const float* __restrict__ bias, float* __restrict__ out)
{
    __shared__ GemmSmem sm;
    const int tid = threadIdx.x;
    const int lane = tid & 31, wid = tid >> 5;
    const int warp_m = wid & 1, warp_n = wid >> 1;
    const int row0 = blockIdx.y * 128, col0 = blockIdx.x * 128;

    float acc[4][4][4];
    #pragma unroll
    for (int i = 0; i < 4; i++)
        #pragma unroll
        for (int j = 0; j < 4; j++)
            #pragma unroll
            for (int k = 0; k < 4; k++) acc[i][j][k] = 0.f;

    hmma_mainloop<3>(gAhi, gAlo, gWout_hi, gWout_lo, sm, row0, col0, acc);

    #pragma unroll
    for (int mt = 0; mt < 4; mt++) {
        #pragma unroll
        for (int nt = 0; nt < 4; nt++) {
            const int c = col0 + warp_n * 32 + nt * 8 + (lane & 3) * 2;
            const float b0 = bias[c], b1 = bias[c + 1];
            #pragma unroll
            for (int half = 0; half < 2; half++) {
                const int r = row0 + warp_m * 64 + mt * 16 + (lane >> 2) + half * 8;
                float2 v = make_float2(acc[mt][nt][half * 2] + b0,
                                       acc[mt][nt][half * 2 + 1] + b1);
                *(float2*)(out + (size_t)r * DD + c) = v;
            }
        }
    }
}

// ---------------------------------------------------------------------------
// Kernel: RoPE. fp32 Q/K in -> rotated single-bf16 out.
// ---------------------------------------------------------------------------
__global__ __launch_bounds__(256) void rope_kernel()
{
    const int idx = blockIdx.x * blockDim.x + threadIdx.x;
    const int t = idx & 31;
    const int l = (idx >> 5) & (LL - 1);
    const int bh = idx >> 16;
    if (bh >= BB * HH) return;

    const float inv_freq = powf(10000.0f, -(float)t / 32.0f);
    const float angle = (float)l * inv_freq;
    const float c = cosf(angle);
    const float s = sinf(angle);

    const size_t base = ((size_t)bh * LL + l) * HD;
    {
        float x1 = g_Q[base + t], x2 = g_Q[base + t + 32];
        gQhi[base + t]      = __float2bfloat16(x1 * c - x2 * s);
        gQhi[base + t + 32] = __float2bfloat16(x2 * c + x1 * s);
    }
    {
        float x1 = g_K[base + t], x2 = g_K[base + t + 32];
        gKhi[base + t]      = __float2bfloat16(x1 * c - x2 * s);
        gKhi[base + t + 32] = __float2bfloat16(x2 * c + x1 * s);
    }
}

// ---------------------------------------------------------------------------
// Kernel: fused causal attention, two-pass (normalized probs written once).
// Pass 1: kt loop of S + exp + rowsums (no V, no PV, no writes).
// Pass 2: kt loop of S + exp*inv -> normalized probs + P smem + PV.
// Block = (qtile 128, h, b), 8 warps.
// ---------------------------------------------------------------------------
struct AttnSmem {
    __nv_bfloat16 Qhi[128][72];
    __nv_bfloat16 Khi[128][72];
    __nv_bfloat16 Vthi[64][136], Vtlo[64][136];
    __nv_bfloat16 Phi[128][136], Plo[128][136];
    float ls[128];
    float inv[128];
};

__global__ __launch_bounds__(256) void attn_mma_kernel(float* __restrict__ probs)
{
    extern __shared__ char smraw[];
    AttnSmem& sm = *(AttnSmem*)smraw;
    const int tid = threadIdx.x, lane = tid & 31, wid = tid >> 5;
    const int warp_m = wid & 1, warp_n = wid >> 1;     // S phase 2x4
    const int warp_om = wid & 3, warp_on = wid >> 2;   // PV phase 4x2
    const int qt = blockIdx.x, h = blockIdx.y, bb = blockIdx.z;
    const int q0 = qt * 128;
    const size_t bh = (size_t)bb * HH + h;

    const __nv_bfloat16* Qhig = gQhi + (bh * LL + q0) * HD;
    const __nv_bfloat16* Khig = gKhi + bh * LL * HD;
    const __nv_bfloat16* Vthig = gVthi + bh * HD * LL;
    const __nv_bfloat16* Vtlog = gVtlo + bh * HD * LL;
    float* Pb = probs + (bh * LL + q0) * LL;

    // Stage Q tile (single bf16, resident all kernel)
    #pragma unroll
    for (int t = 0; t < 4; t++) {
        const int idx = tid + t * 256;
        const int r = idx >> 3, c = (idx & 7) * 8;
        *(uint4*)&sm.Qhi[r][c] = *(const uint4*)(Qhig + r * HD + c);
    }
    if (tid < 128) sm.ls[tid] = 0.f;

    const float scale = rsqrtf(2048.0f);
    __syncthreads();

    // ======================= PASS 1: row sums only =======================
    for (int kt = 0; kt <= qt; kt++) {
        const int k0 = kt * 128;
        #pragma unroll
        for (int t = 0; t < 4; t++) {
            const int idx = tid + t * 256;
            const int r = idx >> 3, c = (idx & 7) * 8;
            *(uint4*)&sm.Khi[r][c] = *(const uint4*)(Khig + (size_t)(k0 + r) * HD + c);
        }
        __syncthreads();

        float sacc[4][4][4];
        #pragma unroll
        for (int i = 0; i < 4; i++)
            #pragma unroll
            for (int j = 0; j < 4; j++)
                #pragma unroll
                for (int k = 0; k < 4; k++) sacc[i][j][k] = 0.f;

        #pragma unroll
        for (int ks = 0; ks < 4; ks++) {
            u32 afh[4][4];
            #pragma unroll
            for (int mt = 0; mt < 4; mt++) {
                const int mr = warp_m * 64 + mt * 16 + (lane & 15);
                const int kc = ks * 16 + (lane >> 4) * 8;
                ldsm4(afh[mt], smem_u32(&sm.Qhi[mr][kc]));
            }
            u32 bfh[2][4];
            #pragma unroll
            for (int np = 0; np < 2; np++) {
                const int nr = warp_n * 32 + np * 16 + ((lane >> 4) << 3) + (lane & 7);
                const int kc = ks * 16 + ((lane >> 3) & 1) * 8;
                ldsm4(bfh[np], smem_u32(&sm.Khi[nr][kc]));
            }
            #pragma unroll
            for (int mt = 0; mt < 4; mt++)
                #pragma unroll
                for (int nt = 0; nt < 4; nt++)
                    mma16816(sacc[mt][nt], afh[mt], &bfh[nt >> 1][(nt & 1) * 2]);
        }

        #pragma unroll
        for (int mt = 0; mt < 4; mt++) {
            const int m0 = warp_m * 64 + mt * 16 + (lane >> 2);
            const int qg0 = q0 + m0, qg1 = qg0 + 8;
            float rs0 = 0.f, rs1 = 0.f;
            #pragma unroll
            for (int nt = 0; nt < 4; nt++) {
                const int kg = k0 + warp_n * 32 + nt * 8 + (lane & 3) * 2;
                const float* c = sacc[mt][nt];
                if (kg     <= qg0) rs0 += __expf(c[0] * scale);
                if (kg + 1 <= qg0) rs0 += __expf(c[1] * scale);
                if (kg     <= qg1) rs1 += __expf(c[2] * scale);
                if (kg + 1 <= qg1) rs1 += __expf(c[3] * scale);
            }
            rs0 += __shfl_xor_sync(0xffffffffu, rs0, 1);
            rs0 += __shfl_xor_sync(0xffffffffu, rs0, 2);
            rs1 += __shfl_xor_sync(0xffffffffu, rs1, 1);
            rs1 += __shfl_xor_sync(0xffffffffu, rs1, 2);
            if ((lane & 3) == 0) {
                atomicAdd(&sm.ls[m0], rs0);
                atomicAdd(&sm.ls[m0 + 8], rs1);
            }
        }
        __syncthreads();
    }

    if (tid < 128) sm.inv[tid] = 1.0f / sm.ls[tid];

    float oacc[2][4][4];
    #pragma unroll
    for (int i = 0; i < 2; i++)
        #pragma unroll
        for (int j = 0; j < 4; j++)
            #pragma unroll
            for (int k = 0; k < 4; k++) oacc[i][j][k] = 0.f;
    __syncthreads();

    // ================= PASS 2: normalized probs + PV =================
    for (int kt = 0; kt <= qt; kt++) {
        const int k0 = kt * 128;
        #pragma unroll
        for (int t = 0; t < 4; t++) {
            const int idx = tid + t * 256;
            {
                const int r = idx >> 3, c = (idx & 7) * 8;
                *(uint4*)&sm.Khi[r][c] = *(const uint4*)(Khig + (size_t)(k0 + r) * HD + c);
            }
            {
                const int r = idx >> 4, c = (idx & 15) * 8;
                *(uint4*)&sm.Vthi[r][c] = *(const uint4*)(Vthig + (size_t)r * LL + k0 + c);
                *(uint4*)&sm.Vtlo[r][c] = *(const uint4*)(Vtlog + (size_t)r * LL + k0 + c);
            }
        }
        __syncthreads();

        float sacc[4][4][4];
        #pragma unroll
        for (int i = 0; i < 4; i++)
            #pragma unroll
            for (int j = 0; j < 4; j++)
                #pragma unroll
                for (int k = 0; k < 4; k++) sacc[i][j][k] = 0.f;

        #pragma unroll
        for (int ks = 0; ks < 4; ks++) {
            u32 afh[4][4];
            #pragma unroll
            for (int mt = 0; mt < 4; mt++) {
                const int mr = warp_m * 64 + mt * 16 + (lane & 15);
                const int kc = ks * 16 + (lane >> 4) * 8;
                ldsm4(afh[mt], smem_u32(&sm.Qhi[mr][kc]));
            }
            u32 bfh[2][4];
            #pragma unroll
            for (int np = 0; np < 2; np++) {
                const int nr = warp_n * 32 + np * 16 + ((lane >> 4) << 3) + (lane & 7);
                const int kc = ks * 16 + ((lane >> 3) & 1) * 8;
                ldsm4(bfh[np], smem_u32(&sm.Khi[nr][kc]));
            }
            #pragma unroll
            for (int mt = 0; mt < 4; mt++)
                #pragma unroll
                for (int nt = 0; nt < 4; nt++)
                    mma16816(sacc[mt][nt], afh[mt], &bfh[nt >> 1][(nt & 1) * 2]);
        }

        // exp * inv -> normalized probs (global) + P (smem bf16 hi/lo)
        #pragma unroll
        for (int mt = 0; mt < 4; mt++) {
            const int m0 = warp_m * 64 + mt * 16 + (lane >> 2);
            const int qg0 = q0 + m0, qg1 = qg0 + 8;
            const float inv0 = sm.inv[m0];
            const float inv1 = sm.inv[m0 + 8];
            #pragma unroll
            for (int nt = 0; nt < 4; nt++) {
                const int n = warp_n * 32 + nt * 8 + (lane & 3) * 2;
                const int kg = k0 + n;
                const float* c = sacc[mt][nt];
                float p0 = (kg     <= qg0) ? __expf(c[0] * scale) * inv0 : 0.f;
                float p1 = (kg + 1 <= qg0) ? __expf(c[1] * scale) * inv0 : 0.f;
                float p2 = (kg     <= qg1) ? __expf(c[2] * scale) * inv1 : 0.f;
                float p3 = (kg + 1 <= qg1) ? __expf(c[3] * scale) * inv1 : 0.f;
                *(float2*)(Pb + (size_t)m0 * LL + kg)       = make_float2(p0, p1);
                *(float2*)(Pb + (size_t)(m0 + 8) * LL + kg) = make_float2(p2, p3);
                __nv_bfloat162 h01 = __float22bfloat162_rn(make_float2(p0, p1));
                __nv_bfloat162 h23 = __float22bfloat162_rn(make_float2(p2, p3));
                __nv_bfloat162 l01 = __float22bfloat162_rn(make_float2(
                    p0 - __bfloat162float(h01.x), p1 - __bfloat162float(h01.y)));
                __nv_bfloat162 l23 = __float22bfloat162_rn(make_float2(
                    p2 - __bfloat162float(h23.x), p3 - __bfloat162float(h23.y)));
                *(__nv_bfloat162*)&sm.Phi[m0][n]     = h01;
                *(__nv_bfloat162*)&sm.Phi[m0 + 8][n] = h23;
                *(__nv_bfloat162*)&sm.Plo[m0][n]     = l01;
                *(__nv_bfloat162*)&sm.Plo[m0 + 8][n] = l23;
            }
        }
        __syncthreads();

        // ---- O += P V (3-term split), warp tile 32x32 ----
        #pragma unroll
        for (int ks = 0; ks < 8; ks++) {
            u32 pfh[2][4], pfl[2][4];
            #pragma unroll
            for (int mt = 0; mt < 2; mt++) {
                const int mr = warp_om * 32 + mt * 16 + (lane & 15);
                const int kc = ks * 16 + (lane >> 4) * 8;
                ldsm4(pfh[mt], smem_u32(&sm.Phi[mr][kc]));
                ldsm4(pfl[mt], smem_u32(&sm.Plo[mr][kc]));
            }
            u32 vfh[2][4], vfl[2][4];
            #pragma unroll
            for (int np = 0; np < 2; np++) {
                const int nr = warp_on * 32 + np * 16 + ((lane >> 4) << 3) + (lane & 7);
                const int kc = ks * 16 + ((lane >> 3) & 1) * 8;
                ldsm4(vfh[np], smem_u32(&sm.Vthi[nr][kc]));
                ldsm4(vfl[np], smem_u32(&sm.Vtlo[nr][kc]));
            }
            #pragma unroll
            for (int mt = 0; mt < 2; mt++) {
                #pragma unroll
                for (int nt = 0; nt < 4; nt++) {
                    const u32* bh_ = &vfh[nt >> 1][(nt & 1) * 2];
                    const u32* bl_ = &vfl[nt >> 1][(nt & 1) * 2];
                    mma16816(oacc[mt][nt], pfh[mt], bh_);
                    mma16816(oacc[mt][nt], pfh[mt], bl_);
                    mma16816(oacc[mt][nt], pfl[mt], bh_);
                }
            }
        }
        __syncthreads();
    }

    // Zero fully-masked probs region (cols >= (qt+1)*128)
    const int zc0 = (qt + 1) * 128;
    if (zc0 < LL) {
        const int w4 = (LL - zc0) >> 2;
        const float4 z = make_float4(0.f, 0.f, 0.f, 0.f);
        for (int idx = tid; idx < 128 * w4; idx += 256) {
            const int r = idx / w4, c = idx - r * w4;
            *(float4*)(Pb + (size_t)r * LL + zc0 + c * 4) = z;
        }
    }

    // Epilogue: O already normalized -> gAhi/gAlo (bf16 split)
    #pragma unroll
    for (int mt = 0; mt < 2; mt++) {
        const int m0 = warp_om * 32 + mt * 16 + (lane >> 2);
        #pragma unroll
        for (int nt = 0; nt < 4; nt++) {
            const int d = warp_on * 32 + nt * 8 + (lane & 3) * 2;
            const float* c = oacc[mt][nt];
            float2 v0 = make_float2(c[0], c[1]);
            float2 v1 = make_float2(c[2], c[3]);
            __nv_bfloat162 h0 = __float22bfloat162_rn(v0);
            __nv_bfloat162 l0 = __float22bfloat162_rn(make_float2(
                v0.x - __bfloat162float(h0.x), v0.y - __bfloat162float(h0.y)));
            __nv_bfloat162 h1 = __float22bfloat162_rn(v1);
            __nv_bfloat162 l1 = __float22bfloat162_rn(make_float2(
                v1.x - __bfloat162float(h1.x), v1.y - __bfloat162float(h1.y)));
            const size_t o0 = ((size_t)(bb * LL + q0 + m0)) * DD + h * HD + d;
            const size_t o1 = ((size_t)(bb * LL + q0 + m0 + 8)) * DD + h * HD + d;
            *(__nv_bfloat162*)(gAhi + o0) = h0;
            *(__nv_bfloat162*)(gAlo + o0) = l0;
            *(__nv_bfloat162*)(gAhi + o1) = h1;
            *(__nv_bfloat162*)(gAlo + o1) = l1;
        }
    }
}

// ---------------------------------------------------------------------------
extern "C" void kernel_launch(void* const* d_in, const int* in_sizes, int n_in,
                              void* d_out, int out_size)
{
    const float* X     = (const float*)d_in[0];
    const float* w_qkv = (const float*)d_in[1];
    const float* b_qkv = (const float*)d_in[2];
    const float* w_out = (const float*)d_in[3];
    const float* b_out = (const float*)d_in[4];

    float* out   = (float*)d_out;
    float* probs = out + (size_t)BB * LL * DD;

    __nv_bfloat16 *xhi, *xlo, *wqh, *wql, *woh, *wol;
    cudaGetSymbolAddress((void**)&xhi, gXhi);
    cudaGetSymbolAddress((void**)&xlo, gXlo);
    cudaGetSymbolAddress((void**)&wqh, gWqkv_hi);
    cudaGetSymbolAddress((void**)&wql, gWqkv_lo);
    cudaGetSymbolAddress((void**)&woh, gWout_hi);
    cudaGetSymbolAddress((void**)&wol, gWout_lo);

    cudaFuncSetAttribute(attn_mma_kernel,
                         cudaFuncAttributeMaxDynamicSharedMemorySize,
                         (int)sizeof(AttnSmem));

    // 0. fp32 -> bf16 hi/lo conversions
    xconv_kernel<<<(BB * LL * DD) / 256, 256>>>(X, xhi, xlo);
    wconv_kernel<<<dim3(ND3 / 32, KDIM / 32), dim3(32, 8)>>>(w_qkv, wqh, wql, KDIM, ND3);
    wconv_kernel<<<dim3(DD / 32, KDIM / 32), dim3(32, 8)>>>(w_out, woh, wol, KDIM, DD);

    // 1. QKV projection (HMMA; Q/K 1-term, V 3-term)
    qkv_mma_kernel<<<dim3(ND3 / 128, (BB * LL) / 128), 256>>>(b_qkv);

    // 2. RoPE (fp32 -> single bf16) and V transpose/split
    rope_kernel<<<(BB * HH * LL * 32) / 256, 256>>>();
    vconv_kernel<<<dim3(LL / 32, HD / 32, BB * HH), dim3(32, 8)>>>();

    // 3. Fused two-pass attention (HMMA, writes normalized probs)
    attn_mma_kernel<<<dim3(LL / 128, HH, BB), 256, sizeof(AttnSmem)>>>(probs);

    // 4. Output projection (HMMA)
    out_mma_kernel<<<dim3(DD / 128, (BB * LL) / 128), 256>>>(b_out, out);
}

// round 14
// speedup vs baseline: 1.0385x; 1.0385x over previous
#include <cuda_runtime.h>
#include <cuda_bf16.h>
#include <cstdint>
#include <math.h>

// Problem constants
#define BB 2
#define LL 2048
#define DD 768
#define HH 12
#define HD 64
#define ND3 2304   // 3*D
#define KDIM 768

typedef unsigned long long u64;
typedef unsigned int u32;

// Scratch (device globals: allocation-free rule)
__device__ float g_Q[BB * HH * LL * HD];
__device__ float g_K[BB * HH * LL * HD];
__device__ float g_V[BB * HH * LL * HD];

// bf16 hi/lo split operands
__device__ __nv_bfloat16 gXhi[BB * LL * DD], gXlo[BB * LL * DD];
__device__ __nv_bfloat16 gWqkv_hi[ND3 * KDIM], gWqkv_lo[ND3 * KDIM];   // [N][K]
__device__ __nv_bfloat16 gWout_hi[DD * KDIM],  gWout_lo[DD * KDIM];    // [N][K]
__device__ __nv_bfloat16 gAhi[BB * LL * DD],   gAlo[BB * LL * DD];
// RoPE'd Q/K, [b][h][l][d] — single bf16 (S-path error budget)
__device__ __nv_bfloat16 gQhi[BB * HH * LL * HD];
__device__ __nv_bfloat16 gKhi[BB * HH * LL * HD];
// V transposed, [b][h][d][l] — hi/lo (PV feeds output directly; keep split)
__device__ __nv_bfloat16 gVthi[BB * HH * HD * LL], gVtlo[BB * HH * HD * LL];

// ---------------------------------------------------------------------------
// PTX helpers
// ---------------------------------------------------------------------------
__device__ __forceinline__ u32 smem_u32(const void* p) {
    u32 a;
    asm("{ .reg .u64 t; cvta.to.shared.u64 t, %1; cvt.u32.u64 %0, t; }"
        : "=r"(a) : "l"(p));
    return a;
}
__device__ __forceinline__ void ldsm4(u32* r, u32 addr) {
    asm volatile("ldmatrix.sync.aligned.m8n8.x4.shared.b16 {%0,%1,%2,%3}, [%4];"
                 : "=r"(r[0]), "=r"(r[1]), "=r"(r[2]), "=r"(r[3]) : "r"(addr));
}
__device__ __forceinline__ void mma16816(float* c, const u32* a, const u32* b) {
    asm volatile(
        "mma.sync.aligned.m16n8k16.row.col.f32.bf16.bf16.f32 "
        "{%0,%1,%2,%3}, {%4,%5,%6,%7}, {%8,%9}, {%0,%1,%2,%3};"
        : "+f"(c[0]), "+f"(c[1]), "+f"(c[2]), "+f"(c[3])
        : "r"(a[0]), "r"(a[1]), "r"(a[2]), "r"(a[3]), "r"(b[0]), "r"(b[1]));
}

__device__ __forceinline__ void split_bf16(float x, __nv_bfloat16& h, __nv_bfloat16& l) {
    h = __float2bfloat16(x);
    l = __float2bfloat16(x - __bfloat162float(h));
}

// ---------------------------------------------------------------------------
// Conversion kernels
// ---------------------------------------------------------------------------
__global__ __launch_bounds__(256) void xconv_kernel(
    const float* __restrict__ src, __nv_bfloat16* __restrict__ hi,
    __nv_bfloat16* __restrict__ lo)
{
    const int i = blockIdx.x * 256 + threadIdx.x;
    __nv_bfloat16 h, l;
    split_bf16(src[i], h, l);
    hi[i] = h; lo[i] = l;
}

// W[K][N] row-major -> hi/lo[N][K] (transposed, bf16 split)
__global__ __launch_bounds__(256) void wconv_kernel(
    const float* __restrict__ W, __nv_bfloat16* __restrict__ hi,
    __nv_bfloat16* __restrict__ lo, int K, int N)
{
    __shared__ float t[32][33];
    const int n0 = blockIdx.x * 32, k0 = blockIdx.y * 32;
    const int tx = threadIdx.x, ty = threadIdx.y;   // 32 x 8
    #pragma unroll
    for (int i = 0; i < 4; i++)
        t[ty + 8 * i][tx] = W[(size_t)(k0 + ty + 8 * i) * N + n0 + tx];
    __syncthreads();
    #pragma unroll
    for (int i = 0; i < 4; i++) {
        const int n = n0 + ty + 8 * i, k = k0 + tx;
        float x = t[tx][ty + 8 * i];
        __nv_bfloat16 h, l;
        split_bf16(x, h, l);
        hi[(size_t)n * K + k] = h;
        lo[(size_t)n * K + k] = l;
    }
}

// g_V [bh][l][64] fp32 -> gVt hi/lo [bh][64][LL] bf16 (transpose + split)
__global__ void vconv_kernel()   // grid (LL/32, HD/32, BH), block (32,8)
{
    __shared__ float t[32][33];
    const int l0 = blockIdx.x * 32, d0 = blockIdx.y * 32;
    const int bh = blockIdx.z;
    const int tx = threadIdx.x, ty = threadIdx.y;
    const float* V = g_V + (size_t)bh * LL * HD;
    #pragma unroll
    for (int i = 0; i < 4; i++)
        t[ty + 8 * i][tx] = V[(size_t)(l0 + ty + 8 * i) * HD + d0 + tx];
    __syncthreads();
    #pragma unroll
    for (int i = 0; i < 4; i++) {
        const int d = d0 + ty + 8 * i, l = l0 + tx;
        float x = t[tx][ty + 8 * i];
        __nv_bfloat16 h, lo_;
        split_bf16(x, h, lo_);
        const size_t o = (size_t)bh * HD * LL + (size_t)d * LL + l;
        gVthi[o] = h;
        gVtlo[o] = lo_;
    }
}

// ---------------------------------------------------------------------------
// HMMA GEMM mainloops: separate 3-term and 1-term versions (separate kernels
// so register allocation stays clean — R12's branched version hit 134 regs).
// ---------------------------------------------------------------------------
struct GemmSmem {
    __nv_bfloat16 A[2][128][40];
    __nv_bfloat16 B[2][128][40];
};
struct GemmSmem1 {
    __nv_bfloat16 A[128][40];
    __nv_bfloat16 B[128][40];
};

__device__ __forceinline__ void hmma_mainloop3(
    const __nv_bfloat16* __restrict__ Ahi, const __nv_bfloat16* __restrict__ Alo,
    const __nv_bfloat16* __restrict__ Bhi, const __nv_bfloat16* __restrict__ Blo,
    GemmSmem& sm, int row0, int col0, float acc[4][4][4])
{
    const int tid = threadIdx.x;
    const int lane = tid & 31, wid = tid >> 5;
    const int warp_m = wid & 1, warp_n = wid >> 1;

    for (int kt = 0; kt < KDIM / 32; kt++) {
        #pragma unroll
        for (int t = 0; t < 2; t++) {
            const int idx = tid + t * 256;
            const int r = idx >> 2, c4 = idx & 3;
            const size_t ga = (size_t)(row0 + r) * KDIM + kt * 32 + c4 * 8;
            const size_t gb = (size_t)(col0 + r) * KDIM + kt * 32 + c4 * 8;
            *(uint4*)&sm.A[0][r][c4 * 8] = *(const uint4*)(Ahi + ga);
            *(uint4*)&sm.A[1][r][c4 * 8] = *(const uint4*)(Alo + ga);
            *(uint4*)&sm.B[0][r][c4 * 8] = *(const uint4*)(Bhi + gb);
            *(uint4*)&sm.B[1][r][c4 * 8] = *(const uint4*)(Blo + gb);
        }
        __syncthreads();

        #pragma unroll
        for (int ks = 0; ks < 2; ks++) {
            u32 afh[4][4], afl[4][4];
            #pragma unroll
            for (int mt = 0; mt < 4; mt++) {
                const int mr = warp_m * 64 + mt * 16 + (lane & 15);
                const int kc = ks * 16 + (lane >> 4) * 8;
                ldsm4(afh[mt], smem_u32(&sm.A[0][mr][kc]));
                ldsm4(afl[mt], smem_u32(&sm.A[1][mr][kc]));
            }
            u32 bfh[2][4], bfl[2][4];
            #pragma unroll
            for (int np = 0; np < 2; np++) {
                const int nr = warp_n * 32 + np * 16 + ((lane >> 4) << 3) + (lane & 7);
                const int kc = ks * 16 + ((lane >> 3) & 1) * 8;
                ldsm4(bfh[np], smem_u32(&sm.B[0][nr][kc]));
                ldsm4(bfl[np], smem_u32(&sm.B[1][nr][kc]));
            }
            #pragma unroll
            for (int mt = 0; mt < 4; mt++) {
                #pragma unroll
                for (int nt = 0; nt < 4; nt++) {
                    const u32* bh = &bfh[nt >> 1][(nt & 1) * 2];
                    const u32* bl = &bfl[nt >> 1][(nt & 1) * 2];
                    mma16816(acc[mt][nt], afh[mt], bh);
                    mma16816(acc[mt][nt], afh[mt], bl);
                    mma16816(acc[mt][nt], afl[mt], bh);
                }
            }
        }
        __syncthreads();
    }
}

__device__ __forceinline__ void hmma_mainloop1(
    const __nv_bfloat16* __restrict__ Ahi, const __nv_bfloat16* __restrict__ Bhi,
    GemmSmem1& sm, int row0, int col0, float acc[4][4][4])
{
    const int tid = threadIdx.x;
    const int lane = tid & 31, wid = tid >> 5;
    const int warp_m = wid & 1, warp_n = wid >> 1;

    for (int kt = 0; kt < KDIM / 32; kt++) {
        #pragma unroll
        for (int t = 0; t < 2; t++) {
            const int idx = tid + t * 256;
            const int r = idx >> 2, c4 = idx & 3;
            const size_t ga = (size_t)(row0 + r) * KDIM + kt * 32 + c4 * 8;
            const size_t gb = (size_t)(col0 + r) * KDIM + kt * 32 + c4 * 8;
            *(uint4*)&sm.A[r][c4 * 8] = *(const uint4*)(Ahi + ga);
            *(uint4*)&sm.B[r][c4 * 8] = *(const uint4*)(Bhi + gb);
        }
        __syncthreads();

        #pragma unroll
        for (int ks = 0; ks < 2; ks++) {
            u32 afh[4][4];
            #pragma unroll
            for (int mt = 0; mt < 4; mt++) {
                const int mr = warp_m * 64 + mt * 16 + (lane & 15);
                const int kc = ks * 16 + (lane >> 4) * 8;
                ldsm4(afh[mt], smem_u32(&sm.A[mr][kc]));
            }
            u32 bfh[2][4];
            #pragma unroll
            for (int np = 0; np < 2; np++) {
                const int nr = warp_n * 32 + np * 16 + ((lane >> 4) << 3) + (lane & 7);
                const int kc = ks * 16 + ((lane >> 3) & 1) * 8;
                ldsm4(bfh[np], smem_u32(&sm.B[nr][kc]));
            }
            #pragma unroll
            for (int mt = 0; mt < 4; mt++)
                #pragma unroll
                for (int nt = 0; nt < 4; nt++)
                    mma16816(acc[mt][nt], afh[mt], &bfh[nt >> 1][(nt & 1) * 2]);
        }
        __syncthreads();
    }
}

// ---------------------------------------------------------------------------
// Kernel: Q/K projection (1-term HMMA). Grid (12, 32).
// ---------------------------------------------------------------------------
__global__ __launch_bounds__(256) void qk_mma_kernel(const float* __restrict__ bias)
{
    __shared__ GemmSmem1 sm;
    const int tid = threadIdx.x;
    const int lane = tid & 31, wid = tid >> 5;
    const int warp_m = wid & 1, warp_n = wid >> 1;
    const int row0 = blockIdx.y * 128, col0 = blockIdx.x * 128;

    float acc[4][4][4];
    #pragma unroll
    for (int i = 0; i < 4; i++)
        #pragma unroll
        for (int j = 0; j < 4; j++)
            #pragma unroll
            for (int k = 0; k < 4; k++) acc[i][j][k] = 0.f;

    hmma_mainloop1(gXhi, gWqkv_hi, sm, row0, col0, acc);

    #pragma unroll
    for (int mt = 0; mt < 4; mt++) {
        #pragma unroll
        for (int nt = 0; nt < 4; nt++) {
            const int c = col0 + warp_n * 32 + nt * 8 + (lane & 3) * 2;
            const int which = c / DD;                 // 0 = Q, 1 = K
            const int rem = c - which * DD;
            const int h = rem >> 6, d = rem & 63;
            float* dst = (which == 0) ? g_Q : g_K;
            const float b0 = bias[c], b1 = bias[c + 1];
            #pragma unroll
            for (int half = 0; half < 2; half++) {
                const int r = row0 + warp_m * 64 + mt * 16 + (lane >> 2) + half * 8;
                const int bb = r >> 11, l = r & 2047;
                float2 v = make_float2(acc[mt][nt][half * 2] + b0,
                                       acc[mt][nt][half * 2 + 1] + b1);
                *(float2*)(dst + (((size_t)(bb * HH + h)) * LL + l) * HD + d) = v;
            }
        }
    }
}

// ---------------------------------------------------------------------------
// Kernel: V projection (3-term HMMA). Grid (6, 32). Columns 1536 + bx*128.
// ---------------------------------------------------------------------------
__global__ __launch_bounds__(256) void v_mma_kernel(const float* __restrict__ bias)
{
    __shared__ GemmSmem sm;
    const int tid = threadIdx.x;
    const int lane = tid & 31, wid = tid >> 5;
    const int warp_m = wid & 1, warp_n = wid >> 1;
    const int row0 = blockIdx.y * 128, col0 = 2 * DD + blockIdx.x * 128;

    float acc[4][4][4];
    #pragma unroll
    for (int i = 0; i < 4; i++)
        #pragma unroll
        for (int j = 0; j < 4; j++)
            #pragma unroll
            for (int k = 0; k < 4; k++) acc[i][j][k] = 0.f;

    hmma_mainloop3(gXhi, gXlo, gWqkv_hi, gWqkv_lo, sm, row0, col0, acc);

    #pragma unroll
    for (int mt = 0; mt < 4; mt++) {
        #pragma unroll
        for (int nt = 0; nt < 4; nt++) {
            const int c = col0 + warp_n * 32 + nt * 8 + (lane & 3) * 2;
            const int rem = c - 2 * DD;
            const int h = rem >> 6, d = rem & 63;
            const float b0 = bias[c], b1 = bias[c + 1];
            #pragma unroll
            for (int half = 0; half < 2; half++) {
                const int r = row0 + warp_m * 64 + mt * 16 + (lane >> 2) + half * 8;
                const int bb = r >> 11, l = r & 2047;
                float2 v = make_float2(acc[mt][nt][half * 2] + b0,
                                       acc[mt][nt][half * 2 + 1] + b1);
                *(float2*)(g_V + (((size_t)(bb * HH + h)) * LL + l) * HD + d) = v;
            }
        }
    }
}

// ---------------------------------------------------------------------------
// Kernel: output projection via HMMA (3-term; feeds output directly).
// ---------------------------------------------------------------------------
__global__ __launch_bounds__(256) void out_mma_kernel(
    const float* __restrict__ bias, float* __restrict__ out)
{
    __shared__ GemmSmem sm;
    const int tid = threadIdx.x;
    const int lane = tid & 31, wid = tid >> 5;
    const int warp_m = wid & 1, warp_n = wid >> 1;
    const int row0 = blockIdx.y * 128, col0 = blockIdx.x * 128;

    float acc[4][4][4];
    #pragma unroll
    for (int i = 0; i < 4; i++)
        #pragma unroll
        for (int j = 0; j < 4; j++)
            #pragma unroll
            for (int k = 0; k < 4; k++) acc[i][j][k] = 0.f;

    hmma_mainloop3(gAhi, gAlo, gWout_hi, gWout_lo, sm, row0, col0, acc);

    #pragma unroll
    for (int mt = 0; mt < 4; mt++) {
        #pragma unroll
        for (int nt = 0; nt < 4; nt++) {
            const int c = col0 + warp_n * 32 + nt * 8 + (lane & 3) * 2;
            const float b0 = bias[c], b1 = bias[c + 1];
            #pragma unroll
            for (int half = 0; half < 2; half++) {
                const int r = row0 + warp_m * 64 + mt * 16 + (lane >> 2) + half * 8;
                float2 v = make_float2(acc[mt][nt][half * 2] + b0,
                                       acc[mt][nt][half * 2 + 1] + b1);
                *(float2*)(out + (size_t)r * DD + c) = v;
            }
        }
    }
}

// ---------------------------------------------------------------------------
// Kernel: RoPE. fp32 Q/K in -> rotated single-bf16 out.
// ---------------------------------------------------------------------------
__global__ __launch_bounds__(256) void rope_kernel()
{
    const int idx = blockIdx.x * blockDim.x + threadIdx.x;
    const int t = idx & 31;
    const int l = (idx >> 5) & (LL - 1);
    const int bh = idx >> 16;
    if (bh >= BB * HH) return;

    const float inv_freq = powf(10000.0f, -(float)t / 32.0f);
    const float angle = (float)l * inv_freq;
    const float c = cosf(angle);
    const float s = sinf(angle);

    const size_t base = ((size_t)bh * LL + l) * HD;
    {
        float x1 = g_Q[base + t], x2 = g_Q[base + t + 32];
        gQhi[base + t]      = __float2bfloat16(x1 * c - x2 * s);
        gQhi[base + t + 32] = __float2bfloat16(x2 * c + x1 * s);
    }
    {
        float x1 = g_K[base + t], x2 = g_K[base + t + 32];
        gKhi[base + t]      = __float2bfloat16(x1 * c - x2 * s);
        gKhi[base + t + 32] = __float2bfloat16(x2 * c + x1 * s);
    }
}

// ---------------------------------------------------------------------------
// Kernel: fused causal attention, two-pass (normalized probs written once).
// ---------------------------------------------------------------------------
struct AttnSmem {
    __nv_bfloat16 Qhi[128][72];
    __nv_bfloat16 Khi[128][72];
    __nv_bfloat16 Vthi[64][136], Vtlo[64][136];
    __nv_bfloat16 Phi[128][136], Plo[128][136];
    float ls[128];
    float inv[128];
};

__global__ __launch_bounds__(256) void attn_mma_kernel(float* __restrict__ probs)
{
    extern __shared__ char smraw[];
    AttnSmem& sm = *(AttnSmem*)smraw;
    const int tid = threadIdx.x, lane = tid & 31, wid = tid >> 5;
    const int warp_m = wid & 1, warp_n = wid >> 1;     // S phase 2x4
    const int warp_om = wid & 3, warp_on = wid >> 2;   // PV phase 4x2
    const int qt = blockIdx.x, h = blockIdx.y, bb = blockIdx.z;
    const int q0 = qt * 128;
    const size_t bh = (size_t)bb * HH + h;

    const __nv_bfloat16* Qhig = gQhi + (bh * LL + q0) * HD;
    const __nv_bfloat16* Khig = gKhi + bh * LL * HD;
    const __nv_bfloat16* Vthig = gVthi + bh * HD * LL;
    const __nv_bfloat16* Vtlog = gVtlo + bh * HD * LL;
    float* Pb = probs + (bh * LL + q0) * LL;

    #pragma unroll
    for (int t = 0; t < 4; t++) {
        const int idx = tid + t * 256;
        const int r = idx >> 3, c = (idx & 7) * 8;
        *(uint4*)&sm.Qhi[r][c] = *(const uint4*)(Qhig + r * HD + c);
    }
    if (tid < 128) sm.ls[tid] = 0.f;

    const float scale = rsqrtf(2048.0f);
    __syncthreads();

    // ======================= PASS 1: row sums only =======================
    for (int kt = 0; kt <= qt; kt++) {
        const int k0 = kt * 128;
        #pragma unroll
        for (int t = 0; t < 4; t++) {
            const int idx = tid + t * 256;
            const int r = idx >> 3, c = (idx & 7) * 8;
            *(uint4*)&sm.Khi[r][c] = *(const uint4*)(Khig + (size_t)(k0 + r) * HD + c);
        }
        __syncthreads();

        float sacc[4][4][4];
        #pragma unroll
        for (int i = 0; i < 4; i++)
            #pragma unroll
            for (int j = 0; j < 4; j++)
                #pragma unroll
                for (int k = 0; k < 4; k++) sacc[i][j][k] = 0.f;

        #pragma unroll
        for (int ks = 0; ks < 4; ks++) {
            u32 afh[4][4];
            #pragma unroll
            for (int mt = 0; mt < 4; mt++) {
                const int mr = warp_m * 64 + mt * 16 + (lane & 15);
                const int kc = ks * 16 + (lane >> 4) * 8;
                ldsm4(afh[mt], smem_u32(&sm.Qhi[mr][kc]));
            }
            u32 bfh[2][4];
            #pragma unroll
            for (int np = 0; np < 2; np++) {
                const int nr = warp_n * 32 + np * 16 + ((lane >> 4) << 3) + (lane & 7);
                const int kc = ks * 16 + ((lane >> 3) & 1) * 8;
                ldsm4(bfh[np], smem_u32(&sm.Khi[nr][kc]));
            }
            #pragma unroll
            for (int mt = 0; mt < 4; mt++)
                #pragma unroll
                for (int nt = 0; nt < 4; nt++)
                    mma16816(sacc[mt][nt], afh[mt], &bfh[nt >> 1][(nt & 1) * 2]);
        }

        #pragma unroll
        for (int mt = 0; mt < 4; mt++) {
            const int m0 = warp_m * 64 + mt * 16 + (lane >> 2);
            const int qg0 = q0 + m0, qg1 = qg0 + 8;
            float rs0 = 0.f, rs1 = 0.f;
            #pragma unroll
            for (int nt = 0; nt < 4; nt++) {
                const int kg = k0 + warp_n * 32 + nt * 8 + (lane & 3) * 2;
                const float* c = sacc[mt][nt];
                if (kg     <= qg0) rs0 += __expf(c[0] * scale);
                if (kg + 1 <= qg0) rs0 += __expf(c[1] * scale);
                if (kg     <= qg1) rs1 += __expf(c[2] * scale);
                if (kg + 1 <= qg1) rs1 += __expf(c[3] * scale);
            }
            rs0 += __shfl_xor_sync(0xffffffffu, rs0, 1);
            rs0 += __shfl_xor_sync(0xffffffffu, rs0, 2);
            rs1 += __shfl_xor_sync(0xffffffffu, rs1, 1);
            rs1 += __shfl_xor_sync(0xffffffffu, rs1, 2);
            if ((lane & 3) == 0) {
                atomicAdd(&sm.ls[m0], rs0);
                atomicAdd(&sm.ls[m0 + 8], rs1);
            }
        }
        __syncthreads();
    }

    if (tid < 128) sm.inv[tid] = 1.0f / sm.ls[tid];

    float oacc[2][4][4];
    #pragma unroll
    for (int i = 0; i < 2; i++)
        #pragma unroll
        for (int j = 0; j < 4; j++)
            #pragma unroll
            for (int k = 0; k < 4; k++) oacc[i][j][k] = 0.f;
    __syncthreads();

    // ================= PASS 2: normalized probs + PV =================
    for (int kt = 0; kt <= qt; kt++) {
        const int k0 = kt * 128;
        #pragma unroll
        for (int t = 0; t < 4; t++) {
            const int idx = tid + t * 256;
            {
                const int r = idx >> 3, c = (idx & 7) * 8;
                *(uint4*)&sm.Khi[r][c] = *(const uint4*)(Khig + (size_t)(k0 + r) * HD + c);
            }
            {
                const int r = idx >> 4, c = (idx & 15) * 8;
                *(uint4*)&sm.Vthi[r][c] = *(const uint4*)(Vthig + (size_t)r * LL + k0 + c);
                *(uint4*)&sm.Vtlo[r][c] = *(const uint4*)(Vtlog + (size_t)r * LL + k0 + c);
            }
        }
        __syncthreads();

        float sacc[4][4][4];
        #pragma unroll
        for (int i = 0; i < 4; i++)
            #pragma unroll
            for (int j = 0; j < 4; j++)
                #pragma unroll
                for (int k = 0; k < 4; k++) sacc[i][j][k] = 0.f;

        #pragma unroll
        for (int ks = 0; ks < 4; ks++) {
            u32 afh[4][4];
            #pragma unroll
            for (int mt = 0; mt < 4; mt++) {
                const int mr = warp_m * 64 + mt * 16 + (lane & 15);
                const int kc = ks * 16 + (lane >> 4) * 8;
                ldsm4(afh[mt], smem_u32(&sm.Qhi[mr][kc]));
            }
            u32 bfh[2][4];
            #pragma unroll
            for (int np = 0; np < 2; np++) {
                const int nr = warp_n * 32 + np * 16 + ((lane >> 4) << 3) + (lane & 7);
                const int kc = ks * 16 + ((lane >> 3) & 1) * 8;
                ldsm4(bfh[np], smem_u32(&sm.Khi[nr][kc]));
            }
            #pragma unroll
            for (int mt = 0; mt < 4; mt++)
                #pragma unroll
                for (int nt = 0; nt < 4; nt++)
                    mma16816(sacc[mt][nt], afh[mt], &bfh[nt >> 1][(nt & 1) * 2]);
        }

        #pragma unroll
        for (int mt = 0; mt < 4; mt++) {
            const int m0 = warp_m * 64 + mt * 16 + (lane >> 2);
            const int qg0 = q0 + m0, qg1 = qg0 + 8;
            const float inv0 = sm.inv[m0];
            const float inv1 = sm.inv[m0 + 8];
            #pragma unroll
            for (int nt = 0; nt < 4; nt++) {
                const int n = warp_n * 32 + nt * 8 + (lane & 3) * 2;
                const int kg = k0 + n;
                const float* c = sacc[mt][nt];
                float p0 = (kg     <= qg0) ? __expf(c[0] * scale) * inv0 : 0.f;
                float p1 = (kg + 1 <= qg0) ? __expf(c[1] * scale) * inv0 : 0.f;
                float p2 = (kg     <= qg1) ? __expf(c[2] * scale) * inv1 : 0.f;
                float p3 = (kg + 1 <= qg1) ? __expf(c[3] * scale) * inv1 : 0.f;
                *(float2*)(Pb + (size_t)m0 * LL + kg)       = make_float2(p0, p1);
                *(float2*)(Pb + (size_t)(m0 + 8) * LL + kg) = make_float2(p2, p3);
                __nv_bfloat162 h01 = __float22bfloat162_rn(make_float2(p0, p1));
                __nv_bfloat162 h23 = __float22bfloat162_rn(make_float2(p2, p3));
                __nv_bfloat162 l01 = __float22bfloat162_rn(make_float2(
                    p0 - __bfloat162float(h01.x), p1 - __bfloat162float(h01.y)));
                __nv_bfloat162 l23 = __float22bfloat162_rn(make_float2(
                    p2 - __bfloat162float(h23.x), p3 - __bfloat162float(h23.y)));
                *(__nv_bfloat162*)&sm.Phi[m0][n]     = h01;
                *(__nv_bfloat162*)&sm.Phi[m0 + 8][n] = h23;
                *(__nv_bfloat162*)&sm.Plo[m0][n]     = l01;
                *(__nv_bfloat162*)&sm.Plo[m0 + 8][n] = l23;
            }
        }
        __syncthreads();

        #pragma unroll
        for (int ks = 0; ks < 8; ks++) {
            u32 pfh[2][4], pfl[2][4];
            #pragma unroll
            for (int mt = 0; mt < 2; mt++) {
                const int mr = warp_om * 32 + mt * 16 + (lane & 15);
                const int kc = ks * 16 + (lane >> 4) * 8;
                ldsm4(pfh[mt], smem_u32(&sm.Phi[mr][kc]));
                ldsm4(pfl[mt], smem_u32(&sm.Plo[mr][kc]));
            }
            u32 vfh[2][4], vfl[2][4];
            #pragma unroll
            for (int np = 0; np < 2; np++) {
                const int nr = warp_on * 32 + np * 16 + ((lane >> 4) << 3) + (lane & 7);
                const int kc = ks * 16 + ((lane >> 3) & 1) * 8;
                ldsm4(vfh[np], smem_u32(&sm.Vthi[nr][kc]));
                ldsm4(vfl[np], smem_u32(&sm.Vtlo[nr][kc]));
            }
            #pragma unroll
            for (int mt = 0; mt < 2; mt++) {
                #pragma unroll
                for (int nt = 0; nt < 4; nt++) {
                    const u32* bh_ = &vfh[nt >> 1][(nt & 1) * 2];
                    const u32* bl_ = &vfl[nt >> 1][(nt & 1) * 2];
                    mma16816(oacc[mt][nt], pfh[mt], bh_);
                    mma16816(oacc[mt][nt], pfh[mt], bl_);
                    mma16816(oacc[mt][nt], pfl[mt], bh_);
                }
            }
        }
        __syncthreads();
    }

    // Zero fully-masked probs region (cols >= (qt+1)*128)
    const int zc0 = (qt + 1) * 128;
    if (zc0 < LL) {
        const int w4 = (LL - zc0) >> 2;
        const float4 z = make_float4(0.f, 0.f, 0.f, 0.f);
        for (int idx = tid; idx < 128 * w4; idx += 256) {
            const int r = idx / w4, c = idx - r * w4;
            *(float4*)(Pb + (size_t)r * LL + zc0 + c * 4) = z;
        }
    }

    // Epilogue: O already normalized -> gAhi/gAlo (bf16 split)
    #pragma unroll
    for (int mt = 0; mt < 2; mt++) {
        const int m0 = warp_om * 32 + mt * 16 + (lane >> 2);
        #pragma unroll
        for (int nt = 0; nt < 4; nt++) {
            const int d = warp_on * 32 + nt * 8 + (lane & 3) * 2;
            const float* c = oacc[mt][nt];
            float2 v0 = make_float2(c[0], c[1]);
            float2 v1 = make_float2(c[2], c[3]);
            __nv_bfloat162 h0 = __float22bfloat162_rn(v0);
            __nv_bfloat162 l0 = __float22bfloat162_rn(make_float2(
                v0.x - __bfloat162float(h0.x), v0.y - __bfloat162float(h0.y)));
            __nv_bfloat162 h1 = __float22bfloat162_rn(v1);
            __nv_bfloat162 l1 = __float22bfloat162_rn(make_float2(
                v1.x - __bfloat162float(h1.x), v1.y - __bfloat162float(h1.y)));
            const size_t o0 = ((size_t)(bb * LL + q0 + m0)) * DD + h * HD + d;
            const size_t o1 = ((size_t)(bb * LL + q0 + m0 + 8)) * DD + h * HD + d;
            *(__nv_bfloat162*)(gAhi + o0) = h0;
            *(__nv_bfloat162*)(gAlo + o0) = l0;
            *(__nv_bfloat162*)(gAhi + o1) = h1;
            *(__nv_bfloat162*)(gAlo + o1) = l1;
        }
    }
}

// ---------------------------------------------------------------------------
extern "C" void kernel_launch(void* const* d_in, const int* in_sizes, int n_in,
                              void* d_out, int out_size)
{
    const float* X     = (const float*)d_in[0];
    const float* w_qkv = (const float*)d_in[1];
    const float* b_qkv = (const float*)d_in[2];
    const float* w_out = (const float*)d_in[3];
    const float* b_out = (const float*)d_in[4];

    float* out   = (float*)d_out;
    float* probs = out + (size_t)BB * LL * DD;

    __nv_bfloat16 *xhi, *xlo, *wqh, *wql, *woh, *wol;
    cudaGetSymbolAddress((void**)&xhi, gXhi);
    cudaGetSymbolAddress((void**)&xlo, gXlo);
    cudaGetSymbolAddress((void**)&wqh, gWqkv_hi);
    cudaGetSymbolAddress((void**)&wql, gWqkv_lo);
    cudaGetSymbolAddress((void**)&woh, gWout_hi);
    cudaGetSymbolAddress((void**)&wol, gWout_lo);

    cudaFuncSetAttribute(attn_mma_kernel,
                         cudaFuncAttributeMaxDynamicSharedMemorySize,
                         (int)sizeof(AttnSmem));

    // 0. fp32 -> bf16 hi/lo conversions
    xconv_kernel<<<(BB * LL * DD) / 256, 256>>>(X, xhi, xlo);
    wconv_kernel<<<dim3(ND3 / 32, KDIM / 32), dim3(32, 8)>>>(w_qkv, wqh, wql, KDIM, ND3);
    wconv_kernel<<<dim3(DD / 32, KDIM / 32), dim3(32, 8)>>>(w_out, woh, wol, KDIM, DD);

    // 1. Q/K projection (1-term) and V projection (3-term)
    qk_mma_kernel<<<dim3(12, (BB * LL) / 128), 256>>>(b_qkv);
    v_mma_kernel<<<dim3(6, (BB * LL) / 128), 256>>>(b_qkv);

    // 2. RoPE (fp32 -> single bf16) and V transpose/split
    rope_kernel<<<(BB * HH * LL * 32) / 256, 256>>>();
    vconv_kernel<<<dim3(LL / 32, HD / 32, BB * HH), dim3(32, 8)>>>();

    // 3. Fused two-pass attention (HMMA, writes normalized probs)
    attn_mma_kernel<<<dim3(LL / 128, HH, BB), 256, sizeof(AttnSmem)>>>(probs);

    // 4. Output projection (HMMA)
    out_mma_kernel<<<dim3(DD / 128, (BB * LL) / 128), 256>>>(b_out, out);
}